// round 2
// baseline (speedup 1.0000x reference)
#include <cuda_runtime.h>

// Problem constants (from reference setup_inputs)
static constexpr int DIM    = 4096;
static constexpr int TOTAL  = 16384;
static constexpr int WIDTH  = 4;
static constexpr int BATCH  = 8;
static constexpr int NSLOTS = 256;
static constexpr int SLEN   = WIDTH - 1;   // 3
static constexpr int TPB    = 256;
static constexpr int TCHUNK = TPB * 4;     // 1024 t-positions per block

// ---------------------------------------------------------------------------
// Main varlen causal conv kernel.
// out[d, t] = sum_k w[d,k] * xx(p - (WIDTH-1-k))  (+ x[d,t] if residual)
// where p = t - seg_start, and xx(q) for q<0 is conv_state[slot, d, SLEN+q]
// (if use_init) else 0.
// ---------------------------------------------------------------------------
__global__ __launch_bounds__(TPB) void conv_main(
    const float* __restrict__ x, const float* __restrict__ w,
    const float* __restrict__ cs, const int* __restrict__ qsl,
    const int* __restrict__ cidx, const int* __restrict__ imode,
    const int* __restrict__ ppad, const int* __restrict__ pres,
    float* __restrict__ out)
{
    __shared__ float sx[4 + TCHUNK];
    __shared__ int   sqsl[BATCH + 1];
    __shared__ int   scidx[BATCH];
    __shared__ int   simode[BATCH];

    const int tid = threadIdx.x;
    const int d   = blockIdx.y;
    const int t0  = blockIdx.x * TCHUNK;

    if (tid < BATCH + 1) sqsl[tid] = qsl[tid];
    if (tid >= 32 && tid < 32 + BATCH) {
        scidx[tid - 32]  = cidx[tid - 32];
        simode[tid - 32] = imode[tid - 32];
    }

    const float4* x4row = reinterpret_cast<const float4*>(x + (size_t)d * TOTAL);
    float4 xv = x4row[t0 / 4 + tid];
    reinterpret_cast<float4*>(sx + 4)[tid] = xv;
    if (tid == 0) {
        float4 h = make_float4(0.f, 0.f, 0.f, 0.f);
        if (t0 >= 4) h = x4row[t0 / 4 - 1];
        reinterpret_cast<float4*>(sx)[0] = h;
    }
    __syncthreads();

    const int   pad = *ppad;
    const int   res = *pres;
    const float4 wv = reinterpret_cast<const float4*>(w)[d];

    const int tbase = t0 + tid * 4;
    const int li    = 4 + tid * 4;   // smem index of x[tbase]

    // segment ids via unrolled scan (searchsorted(qsl, t, 'right') - 1)
    int seg0 = 0, seg3 = 0;
    #pragma unroll
    for (int s = 1; s < BATCH; s++) {
        seg0 += (sqsl[s] <= tbase)     ? 1 : 0;
        seg3 += (sqsl[s] <= tbase + 3) ? 1 : 0;
    }

    float4 o;
    if (seg0 == seg3 && (tbase - sqsl[seg0]) >= SLEN) {
        // fast path: whole 7-tap window inside one segment
        float a0 = sx[li - 3], a1 = sx[li - 2], a2 = sx[li - 1];
        o.x = wv.x * a0   + wv.y * a1   + wv.z * a2   + wv.w * xv.x;
        o.y = wv.x * a1   + wv.y * a2   + wv.z * xv.x + wv.w * xv.y;
        o.z = wv.x * a2   + wv.y * xv.x + wv.z * xv.y + wv.w * xv.z;
        o.w = wv.x * xv.x + wv.y * xv.y + wv.z * xv.z + wv.w * xv.w;
        if (res) { o.x += xv.x; o.y += xv.y; o.z += xv.z; o.w += xv.w; }
    } else {
        float tmp[4];
        float wk[4] = {wv.x, wv.y, wv.z, wv.w};
        #pragma unroll
        for (int i = 0; i < 4; i++) {
            int t = tbase + i;
            int seg = 0;
            #pragma unroll
            for (int s = 1; s < BATCH; s++) seg += (sqsl[s] <= t) ? 1 : 0;
            int  p        = t - sqsl[seg];
            int  slot     = scidx[seg];
            bool valid    = (slot != pad);
            bool use_init = valid && (simode[seg] != 0);
            const float* st = cs + ((size_t)(valid ? slot : 0) * DIM + d) * SLEN;

            float acc = 0.f;
            #pragma unroll
            for (int k = 0; k < WIDTH; k++) {
                int delay = WIDTH - 1 - k;
                int q = p - delay;
                float v;
                if (q >= 0) {
                    v = sx[li + i - delay];
                } else {
                    v = use_init ? st[SLEN + q] : 0.f;
                }
                acc += wk[k] * v;
            }
            if (res) acc += sx[li + i];
            tmp[i] = acc;
        }
        o = make_float4(tmp[0], tmp[1], tmp[2], tmp[3]);
    }

    reinterpret_cast<float4*>(out + (size_t)d * TOTAL)[t0 / 4 + tid] = o;
}

// ---------------------------------------------------------------------------
// Copy conv_states (unchanged slots must survive in the output).
// NSLOTS*DIM*SLEN = 3,145,728 floats = 786,432 float4.
// ---------------------------------------------------------------------------
__global__ void cs_copy(const float4* __restrict__ in, float4* __restrict__ outp)
{
    int i = blockIdx.x * blockDim.x + threadIdx.x;
    outp[i] = in[i];
}

// ---------------------------------------------------------------------------
// Scatter-update the BATCH touched slots with the new tail states.
// new_state[b][d][j] = (L+j >= SLEN) ? x[d, end-SLEN+j]
//                                    : (init ? old_state[slot][d][L+j] : 0)
// ---------------------------------------------------------------------------
__global__ void cs_update(const float* __restrict__ x, const float* __restrict__ cs,
                          const int* __restrict__ qsl, const int* __restrict__ cidx,
                          const int* __restrict__ imode, const int* __restrict__ ppad,
                          float* __restrict__ out_cs)
{
    int b    = blockIdx.x;
    int pad  = *ppad;
    int slot = cidx[b];
    if (slot == pad) return;
    int  start = qsl[b];
    int  end   = qsl[b + 1];
    int  L     = end - start;
    bool binit = (imode[b] != 0);

    for (int idx = threadIdx.x; idx < DIM * SLEN; idx += blockDim.x) {
        int d = idx / SLEN;
        int j = idx % SLEN;
        float v;
        if (L + j >= SLEN) {
            v = x[(size_t)d * TOTAL + (end - SLEN + j)];
        } else {
            v = binit ? cs[((size_t)slot * DIM + d) * SLEN + (L + j)] : 0.f;
        }
        out_cs[(size_t)slot * DIM * SLEN + idx] = v;
    }
}

extern "C" void kernel_launch(void* const* d_in, const int* in_sizes, int n_in,
                              void* d_out, int out_size)
{
    const float* x     = (const float*)d_in[0];
    const float* w     = (const float*)d_in[1];
    const float* cs    = (const float*)d_in[2];
    const int*   qsl   = (const int*)d_in[3];
    const int*   cidx  = (const int*)d_in[4];
    const int*   imode = (const int*)d_in[5];
    const int*   ppad  = (const int*)d_in[6];
    const int*   pres  = (const int*)d_in[7];

    float* out    = (float*)d_out;
    float* out_cs = out + (size_t)DIM * TOTAL;

    dim3 grid(TOTAL / TCHUNK, DIM);
    conv_main<<<grid, TPB>>>(x, w, cs, qsl, cidx, imode, ppad, pres, out);

    int n4 = NSLOTS * DIM * SLEN / 4;
    cs_copy<<<(n4 + 255) / 256, 256>>>((const float4*)cs, (float4*)out_cs);

    cs_update<<<BATCH, 256>>>(x, cs, qsl, cidx, imode, ppad, out_cs);
}

// round 6
// speedup vs baseline: 1.7277x; 1.7277x over previous
#include <cuda_runtime.h>

static constexpr int DIM    = 4096;
static constexpr int TOTAL  = 16384;
static constexpr int WIDTH  = 4;
static constexpr int BATCH  = 8;
static constexpr int NSLOTS = 256;
static constexpr int SLEN   = WIDTH - 1;        // 3
static constexpr int TPB    = 256;
static constexpr int VEC    = 4;                // float4s per thread
static constexpr int TCHUNK = TPB * 4 * VEC;    // 4096 t per block

// ---------------------------------------------------------------------------
// Main varlen causal conv. grid = (TOTAL/TCHUNK, DIM).
// ---------------------------------------------------------------------------
__global__ __launch_bounds__(TPB) void conv_main(
    const float* __restrict__ x, const float* __restrict__ w,
    const float* __restrict__ cs, const int* __restrict__ qsl,
    const int* __restrict__ cidx, const int* __restrict__ imode,
    const int* __restrict__ ppad, const int* __restrict__ pres,
    float* __restrict__ out)
{
    __shared__ float sx[4 + TCHUNK];
    __shared__ int   sqsl[BATCH + 1];
    __shared__ int   scidx[BATCH];
    __shared__ int   simode[BATCH];

    const int tid = threadIdx.x;
    const int d   = blockIdx.y;
    const int t0  = blockIdx.x * TCHUNK;

    if (tid < BATCH + 1) sqsl[tid] = qsl[tid];
    if (tid >= 32 && tid < 32 + BATCH) {
        scidx[tid - 32]  = cidx[tid - 32];
        simode[tid - 32] = imode[tid - 32];
    }

    const float4* x4row = reinterpret_cast<const float4*>(x + (size_t)d * TOTAL);
    float4 xr[VEC];
    #pragma unroll
    for (int j = 0; j < VEC; j++) {
        xr[j] = x4row[t0 / 4 + j * TPB + tid];
        reinterpret_cast<float4*>(sx + 4)[j * TPB + tid] = xr[j];
    }
    if (tid == 0) {
        float4 h = make_float4(0.f, 0.f, 0.f, 0.f);
        if (t0 >= 4) h = x4row[t0 / 4 - 1];
        reinterpret_cast<float4*>(sx)[0] = h;
    }
    __syncthreads();

    // qsl boundaries into registers for the fast-path test
    int qs[BATCH];
    #pragma unroll
    for (int s = 1; s < BATCH; s++) qs[s] = sqsl[s];

    const int    pad = *ppad;
    const float4 wv  = reinterpret_cast<const float4*>(w)[d];
    const float  w3  = wv.w + ((*pres) ? 1.0f : 0.0f);  // residual folded

    float4* out4row = reinterpret_cast<float4*>(out + (size_t)d * TOTAL);

    #pragma unroll
    for (int j = 0; j < VEC; j++) {
        const int ti    = j * TPB + tid;     // float4 index within chunk
        const int tbase = t0 + ti * 4;
        const int li    = 4 + ti * 4;        // smem index of x[tbase]
        const float4 xv = xr[j];

        // fast ⟺ tbase>=3 and no boundary qsl[s] in [tbase-2, tbase+3]
        bool fast = (tbase >= 3);
        #pragma unroll
        for (int s = 1; s < BATCH; s++)
            fast = fast && ((unsigned)(qs[s] - (tbase - 2)) > 5u);

        float4 o;
        if (fast) {
            const float4 pv = *reinterpret_cast<const float4*>(sx + li - 4);
            o.x = wv.x * pv.y + wv.y * pv.z + wv.z * pv.w + w3 * xv.x;
            o.y = wv.x * pv.z + wv.y * pv.w + wv.z * xv.x + w3 * xv.y;
            o.z = wv.x * pv.w + wv.y * xv.x + wv.z * xv.y + w3 * xv.z;
            o.w = wv.x * xv.x + wv.y * xv.y + wv.z * xv.z + w3 * xv.w;
        } else {
            float tmp[4];
            const float wk[4] = {wv.x, wv.y, wv.z, w3};
            #pragma unroll
            for (int i = 0; i < 4; i++) {
                const int t = tbase + i;
                int seg = 0;
                #pragma unroll
                for (int s = 1; s < BATCH; s++) seg += (sqsl[s] <= t) ? 1 : 0;
                const int  p        = t - sqsl[seg];
                const int  slot     = scidx[seg];
                const bool valid    = (slot != pad);
                const bool use_init = valid && (simode[seg] != 0);
                const float* st = cs + ((size_t)(valid ? slot : 0) * DIM + d) * SLEN;

                float acc = 0.f;
                #pragma unroll
                for (int k = 0; k < WIDTH; k++) {
                    const int delay = WIDTH - 1 - k;
                    const int q = p - delay;
                    float v;
                    if (q >= 0) v = sx[li + i - delay];
                    else        v = use_init ? st[SLEN + q] : 0.f;
                    acc += wk[k] * v;
                }
                tmp[i] = acc;
            }
            o = make_float4(tmp[0], tmp[1], tmp[2], tmp[3]);
        }
        out4row[t0 / 4 + ti] = o;
    }
}

// ---------------------------------------------------------------------------
// Fused conv_state copy + update. grid = NSLOTS*DIM/TPB = 4096 blocks.
// Thread <-> (slot, d). Untouched slots: straight copy. Touched slots:
// new_state[d][j] = (L+j>=SLEN) ? x[d, end-SLEN+j] : (init ? old[L+j] : 0)
// ---------------------------------------------------------------------------
__global__ __launch_bounds__(TPB) void cs_out_kernel(
    const float* __restrict__ x, const float* __restrict__ cs,
    const int* __restrict__ qsl, const int* __restrict__ cidx,
    const int* __restrict__ imode, const int* __restrict__ ppad,
    float* __restrict__ out_cs)
{
    __shared__ int sqsl[BATCH + 1];
    __shared__ int scidx[BATCH];
    __shared__ int simode[BATCH];

    const int tid = threadIdx.x;
    if (tid < BATCH + 1) sqsl[tid] = qsl[tid];
    if (tid >= 32 && tid < 32 + BATCH) {
        scidx[tid - 32]  = cidx[tid - 32];
        simode[tid - 32] = imode[tid - 32];
    }
    __syncthreads();

    constexpr int BLK_PER_SLOT = DIM / TPB;            // 16
    const int slot = blockIdx.x / BLK_PER_SLOT;
    const int d    = (blockIdx.x % BLK_PER_SLOT) * TPB + tid;
    const int pad  = *ppad;

    int b = -1;
    #pragma unroll
    for (int s = 0; s < BATCH; s++)
        if (scidx[s] == slot && scidx[s] != pad) b = s;

    const size_t base = ((size_t)slot * DIM + d) * SLEN;

    if (b < 0) {
        out_cs[base + 0] = cs[base + 0];
        out_cs[base + 1] = cs[base + 1];
        out_cs[base + 2] = cs[base + 2];
    } else {
        const int  start = sqsl[b];
        const int  end   = sqsl[b + 1];
        const int  L     = end - start;
        const bool binit = (simode[b] != 0);
        #pragma unroll
        for (int j = 0; j < SLEN; j++) {
            float v;
            if (L + j >= SLEN) v = x[(size_t)d * TOTAL + (end - SLEN + j)];
            else               v = binit ? cs[base + (L + j)] : 0.f;
            out_cs[base + j] = v;
        }
    }
}

extern "C" void kernel_launch(void* const* d_in, const int* in_sizes, int n_in,
                              void* d_out, int out_size)
{
    const float* x     = (const float*)d_in[0];
    const float* w     = (const float*)d_in[1];
    const float* cs    = (const float*)d_in[2];
    const int*   qsl   = (const int*)d_in[3];
    const int*   cidx  = (const int*)d_in[4];
    const int*   imode = (const int*)d_in[5];
    const int*   ppad  = (const int*)d_in[6];
    const int*   pres  = (const int*)d_in[7];

    float* out    = (float*)d_out;
    float* out_cs = out + (size_t)DIM * TOTAL;

    dim3 grid(TOTAL / TCHUNK, DIM);
    conv_main<<<grid, TPB>>>(x, w, cs, qsl, cidx, imode, ppad, pres, out);

    cs_out_kernel<<<NSLOTS * DIM / TPB, TPB>>>(x, cs, qsl, cidx, imode, ppad, out_cs);
}

// round 11
// speedup vs baseline: 1.8189x; 1.0528x over previous
#include <cuda_runtime.h>

static constexpr int DIM    = 4096;
static constexpr int TOTAL  = 16384;
static constexpr int WIDTH  = 4;
static constexpr int BATCH  = 8;
static constexpr int NSLOTS = 256;
static constexpr int SLEN   = WIDTH - 1;        // 3
static constexpr int TPB    = 256;
static constexpr int VEC    = 4;                // float4s per thread
static constexpr int TCHUNK = TPB * 4 * VEC;    // 4096 t per block

static constexpr int NBLK_CS   = NSLOTS * DIM * SLEN / 4 / TPB;  // 3072
static constexpr int NBLK_CONV = (TOTAL / TCHUNK) * DIM;         // 16384
static constexpr int CHUNKS    = TOTAL / TCHUNK;                 // 4

// ---------------------------------------------------------------------------
// Fused kernel. blockIdx.x < NBLK_CS  -> conv_state copy/update part
//               blockIdx.x >= NBLK_CS -> main conv part
// The two parts touch disjoint outputs; cs blocks are placed first so their
// small traffic overlaps conv_main's stream instead of serializing after it.
// ---------------------------------------------------------------------------
__global__ __launch_bounds__(TPB) void fused_kernel(
    const float* __restrict__ x, const float* __restrict__ w,
    const float* __restrict__ cs, const int* __restrict__ qsl,
    const int* __restrict__ cidx, const int* __restrict__ imode,
    const int* __restrict__ ppad, const int* __restrict__ pres,
    float* __restrict__ out, float* __restrict__ out_cs)
{
    __shared__ float sx[4 + TCHUNK];
    __shared__ int   sqsl[BATCH + 1];
    __shared__ int   scidx[BATCH];
    __shared__ int   simode[BATCH];

    const int tid = threadIdx.x;

    if (tid < BATCH + 1) sqsl[tid] = qsl[tid];
    if (tid >= 32 && tid < 32 + BATCH) {
        scidx[tid - 32]  = cidx[tid - 32];
        simode[tid - 32] = imode[tid - 32];
    }

    if (blockIdx.x < NBLK_CS) {
        // ------------------- conv_state copy + update part -------------------
        __syncthreads();
        constexpr int PER_SLOT = DIM * SLEN;            // 12288 floats
        const int i4   = blockIdx.x * TPB + tid;        // float4 index
        const int f    = i4 * 4;                        // float index
        const int slot = f / PER_SLOT;
        const int pad  = *ppad;

        int b = -1;
        #pragma unroll
        for (int s = 0; s < BATCH; s++)
            if (scidx[s] == slot && scidx[s] != pad) b = s;

        const float4* in4  = reinterpret_cast<const float4*>(cs);
        float4*       out4 = reinterpret_cast<float4*>(out_cs);

        if (b < 0) {
            out4[i4] = in4[i4];
        } else {
            const int  end   = sqsl[b + 1];
            const int  L     = end - sqsl[b];
            const bool binit = (simode[b] != 0);
            const int  e0    = f - slot * PER_SLOT;     // element within slot

            float tmp[4];
            #pragma unroll
            for (int r = 0; r < 4; r++) {
                const int e = e0 + r;
                const int d = e / SLEN;
                const int j = e - d * SLEN;
                float v;
                if (L + j >= SLEN) v = x[(size_t)d * TOTAL + (end - SLEN + j)];
                else               v = binit ? cs[(size_t)slot * PER_SLOT + d * SLEN + (L + j)] : 0.f;
                tmp[r] = v;
            }
            out4[i4] = make_float4(tmp[0], tmp[1], tmp[2], tmp[3]);
        }
        return;
    }

    // --------------------------- main conv part ---------------------------
    const int cbid = blockIdx.x - NBLK_CS;
    const int d    = cbid / CHUNKS;
    const int t0   = (cbid % CHUNKS) * TCHUNK;

    const float4* x4row = reinterpret_cast<const float4*>(x + (size_t)d * TOTAL);
    float4 xr[VEC];
    #pragma unroll
    for (int j = 0; j < VEC; j++) {
        xr[j] = __ldcs(&x4row[t0 / 4 + j * TPB + tid]);
        reinterpret_cast<float4*>(sx + 4)[j * TPB + tid] = xr[j];
    }
    if (tid == 0) {
        float4 h = make_float4(0.f, 0.f, 0.f, 0.f);
        if (t0 >= 4) h = __ldg(&x4row[t0 / 4 - 1]);
        reinterpret_cast<float4*>(sx)[0] = h;
    }
    __syncthreads();

    // qsl boundaries into registers for the fast-path test
    int qs[BATCH];
    #pragma unroll
    for (int s = 1; s < BATCH; s++) qs[s] = sqsl[s];

    const int    pad = *ppad;
    const float4 wv  = reinterpret_cast<const float4*>(w)[d];
    const float  w3  = wv.w + ((*pres) ? 1.0f : 0.0f);  // residual folded

    float4* out4row = reinterpret_cast<float4*>(out + (size_t)d * TOTAL);

    #pragma unroll
    for (int j = 0; j < VEC; j++) {
        const int ti    = j * TPB + tid;     // float4 index within chunk
        const int tbase = t0 + ti * 4;
        const int li    = 4 + ti * 4;        // smem index of x[tbase]
        const float4 xv = xr[j];

        // fast ⟺ tbase>=3 and no boundary qsl[s] in [tbase-2, tbase+3]
        bool fast = (tbase >= 3);
        #pragma unroll
        for (int s = 1; s < BATCH; s++)
            fast = fast && ((unsigned)(qs[s] - (tbase - 2)) > 5u);

        float4 o;
        if (fast) {
            const float4 pv = *reinterpret_cast<const float4*>(sx + li - 4);
            o.x = wv.x * pv.y + wv.y * pv.z + wv.z * pv.w + w3 * xv.x;
            o.y = wv.x * pv.z + wv.y * pv.w + wv.z * xv.x + w3 * xv.y;
            o.z = wv.x * pv.w + wv.y * xv.x + wv.z * xv.y + w3 * xv.z;
            o.w = wv.x * xv.x + wv.y * xv.y + wv.z * xv.z + w3 * xv.w;
        } else {
            float tmp[4];
            const float wk[4] = {wv.x, wv.y, wv.z, w3};
            #pragma unroll
            for (int i = 0; i < 4; i++) {
                const int t = tbase + i;
                int seg = 0;
                #pragma unroll
                for (int s = 1; s < BATCH; s++) seg += (sqsl[s] <= t) ? 1 : 0;
                const int  p        = t - sqsl[seg];
                const int  slot     = scidx[seg];
                const bool valid    = (slot != pad);
                const bool use_init = valid && (simode[seg] != 0);
                const float* st = cs + ((size_t)(valid ? slot : 0) * DIM + d) * SLEN;

                float acc = 0.f;
                #pragma unroll
                for (int k = 0; k < WIDTH; k++) {
                    const int delay = WIDTH - 1 - k;
                    const int q = p - delay;
                    float v;
                    if (q >= 0) v = sx[li + i - delay];
                    else        v = use_init ? st[SLEN + q] : 0.f;
                    acc += wk[k] * v;
                }
                tmp[i] = acc;
            }
            o = make_float4(tmp[0], tmp[1], tmp[2], tmp[3]);
        }
        __stcs(&out4row[t0 / 4 + ti], o);
    }
}

extern "C" void kernel_launch(void* const* d_in, const int* in_sizes, int n_in,
                              void* d_out, int out_size)
{
    const float* x     = (const float*)d_in[0];
    const float* w     = (const float*)d_in[1];
    const float* cs    = (const float*)d_in[2];
    const int*   qsl   = (const int*)d_in[3];
    const int*   cidx  = (const int*)d_in[4];
    const int*   imode = (const int*)d_in[5];
    const int*   ppad  = (const int*)d_in[6];
    const int*   pres  = (const int*)d_in[7];

    float* out    = (float*)d_out;
    float* out_cs = out + (size_t)DIM * TOTAL;

    fused_kernel<<<NBLK_CS + NBLK_CONV, TPB>>>(x, w, cs, qsl, cidx, imode,
                                               ppad, pres, out, out_cs);
}